// round 14
// baseline (speedup 1.0000x reference)
#include <cuda_runtime.h>
#include <cuda_fp16.h>
#include <math.h>

#define T_TOK 8192
#define D_DIM 768
#define H_DIM 3072
#define E_NUM 8
#define RBLK 1024   // routing grid blocks

// ---------------- device scratch (no allocations allowed) ----------------
__device__ unsigned g_xh[T_TOK * (D_DIM / 2)];          // x fp16 [t][kp]
__device__ unsigned g_w1h[E_NUM * (D_DIM / 2) * H_DIM]; // W1 fp16 [e][kp][n]
__device__ unsigned g_w2h[E_NUM * (H_DIM / 2) * D_DIM]; // W2 fp16 [e][kp][n]
__device__ unsigned g_hh[T_TOK * (H_DIM / 2)];          // hidden fp16 (compact rows)
__device__ int   g_gate[T_TOK];
__device__ float g_psel[T_TOK];
__device__ unsigned long long g_blk_psum[RBLK * E_NUM]; // per-block partials
__device__ int   g_off[E_NUM + 1];
__device__ int   g_perm[T_TOK];

#define PROB_SCALE 4294967296.0

// ---------------- helpers ----------------
__device__ __forceinline__ unsigned pack2h(float v0, float v1) {
    __half2 h = __floats2half2_rn(v0, v1);
    return *(unsigned*)&h;
}
__device__ __forceinline__ float gelu_exact(float v) {
    return 0.5f * v * (1.0f + erff(v * 0.70710678118654752f));
}
__device__ __forceinline__ void mma16816h(float c[4], const unsigned a[4],
                                          unsigned b0, unsigned b1) {
    asm volatile(
        "mma.sync.aligned.m16n8k16.row.col.f32.f16.f16.f32 "
        "{%0,%1,%2,%3}, {%4,%5,%6,%7}, {%8,%9}, {%0,%1,%2,%3};\n"
        : "+f"(c[0]), "+f"(c[1]), "+f"(c[2]), "+f"(c[3])
        : "r"(a[0]), "r"(a[1]), "r"(a[2]), "r"(a[3]), "r"(b0), "r"(b1));
}
__device__ __forceinline__ void cp16(unsigned dst, const void* src) {
    asm volatile("cp.async.cg.shared.global [%0], [%1], 16;\n" :: "r"(dst), "l"(src));
}

// ---------------- K1: routing (1 warp/token) + fused x->fp16 ----------------
__global__ void routing_kernel(const float* __restrict__ x,
                               const float* __restrict__ gw) {
    __shared__ unsigned long long s_probsum[E_NUM];
    int tid = threadIdx.x;
    if (tid < E_NUM) s_probsum[tid] = 0ull;
    __syncthreads();

    int warp = tid >> 5, lane = tid & 31;
    int t = blockIdx.x * 8 + warp;

    float acc[E_NUM];
#pragma unroll
    for (int e = 0; e < E_NUM; e++) acc[e] = 0.f;
    const float* xr = x + (size_t)t * D_DIM;
    for (int kp = lane; kp < D_DIM / 2; kp += 32) {
        float2 v = ((const float2*)xr)[kp];
        g_xh[(size_t)t * (D_DIM / 2) + kp] = pack2h(v.x, v.y);
        const float* g0 = gw + (2 * kp) * E_NUM;
#pragma unroll
        for (int e = 0; e < E_NUM; e++)
            acc[e] += v.x * g0[e] + v.y * g0[e + E_NUM];
    }
#pragma unroll
    for (int off = 16; off > 0; off >>= 1) {
#pragma unroll
        for (int e = 0; e < E_NUM; e++)
            acc[e] += __shfl_xor_sync(0xffffffffu, acc[e], off);
    }

    if (lane == 0) {
        float mx = acc[0]; int am = 0;
#pragma unroll
        for (int e = 1; e < E_NUM; e++) if (acc[e] > mx) { mx = acc[e]; am = e; }
        float p[E_NUM]; float s = 0.f;
#pragma unroll
        for (int e = 0; e < E_NUM; e++) { p[e] = expf(acc[e] - mx); s += p[e]; }
        float inv = 1.f / s;
#pragma unroll
        for (int e = 0; e < E_NUM; e++) {
            double pq = (double)(p[e] * inv) * PROB_SCALE;
            atomicAdd(&s_probsum[e], (unsigned long long)(pq + 0.5));
        }
        g_gate[t] = am;
        g_psel[t] = p[am] * inv;
    }
    __syncthreads();
    if (tid < E_NUM)
        g_blk_psum[blockIdx.x * E_NUM + tid] = s_probsum[tid];
}

// ---------------- K2: deterministic scan -> sorted perm + loss + tail --------
__global__ void __launch_bounds__(1024) finscat_kernel(float* __restrict__ out,
                                                       int out_size) {
    __shared__ unsigned long long s0[1024], s1[1024];
    const int tid = threadIdx.x;
    const int t0 = tid * 8;

    // per-thread counts over 8 contiguous tokens
    int ge[8];
    int c[E_NUM];
#pragma unroll
    for (int e = 0; e < E_NUM; e++) c[e] = 0;
#pragma unroll
    for (int i = 0; i < 8; i++) { ge[i] = g_gate[t0 + i]; c[ge[i]]++; }

    unsigned long long p0 = 0, p1 = 0;
#pragma unroll
    for (int e = 0; e < 4; e++) {
        p0 |= (unsigned long long)c[e]     << (16 * e);
        p1 |= (unsigned long long)c[e + 4] << (16 * e);
    }
    s0[tid] = p0; s1[tid] = p1;
    __syncthreads();

    // Hillis-Steele inclusive scan (packed 8x16-bit, max 8192 < 65536)
    for (int off = 1; off < 1024; off <<= 1) {
        unsigned long long a0 = 0, a1 = 0;
        if (tid >= off) { a0 = s0[tid - off]; a1 = s1[tid - off]; }
        __syncthreads();
        s0[tid] += a0; s1[tid] += a1;
        __syncthreads();
    }
    const unsigned long long tot0 = s0[1023], tot1 = s1[1023];
    const unsigned long long inc0 = s0[tid],  inc1 = s1[tid];

    int cnt[E_NUM], excl[E_NUM];
#pragma unroll
    for (int e = 0; e < 4; e++) {
        cnt[e]      = (int)((tot0 >> (16 * e)) & 0xFFFF);
        cnt[e + 4]  = (int)((tot1 >> (16 * e)) & 0xFFFF);
        excl[e]     = (int)((inc0 >> (16 * e)) & 0xFFFF) - c[e];
        excl[e + 4] = (int)((inc1 >> (16 * e)) & 0xFFFF) - c[e + 4];
    }
    int offp[E_NUM]; int run = 0;
#pragma unroll
    for (int e = 0; e < E_NUM; e++) { offp[e] = run; run += cnt[e]; }

    // psum reduce (deterministic tree): expert = tid>>7, 128 threads each
    __syncthreads();
    {
        unsigned long long ps = 0;
        const int e = tid >> 7, j = tid & 127;
        for (int i = j; i < RBLK; i += 128) ps += g_blk_psum[i * E_NUM + e];
        s0[tid] = ps;
        __syncthreads();
        for (int st = 64; st > 0; st >>= 1) {
            if (j < st) s0[tid] += s0[tid + st];
            __syncthreads();
        }
    }

    if (tid == 0) {
#pragma unroll
        for (int e = 0; e < E_NUM; e++) g_off[e] = offp[e];
        g_off[E_NUM] = T_TOK;

        float loss = 0.f;
        const float invT = 1.0f / (float)T_TOK;
#pragma unroll
        for (int e = 0; e < E_NUM; e++) {
            float ps = (float)((double)s0[e << 7] / PROB_SCALE);
            loss += (ps * invT) * ((float)cnt[e] * invT);
        }
        loss *= (float)E_NUM;

        int base = T_TOK * D_DIM;
        if (out_size > base) out[base] = loss;
#pragma unroll
        for (int e = 0; e < E_NUM; e++)
            if (out_size > base + 1 + e) out[base + 1 + e] = (float)cnt[e];
    }

    // write sorted-by-token permutation
    int cur[E_NUM];
#pragma unroll
    for (int e = 0; e < E_NUM; e++) cur[e] = offp[e] + excl[e];
#pragma unroll
    for (int i = 0; i < 8; i++) {
        int e = ge[i];
        g_perm[cur[e]++] = t0 + i;
    }
}

// ---------------- K5: weights -> fp16 k-pair packed [e][kp][n] ----------------
template <int WHICH>
__global__ void conv_w_kernel(const float* __restrict__ W) {
    constexpr int KHALF = (WHICH == 1) ? D_DIM / 2 : H_DIM / 2;
    constexpr int NDIM  = (WHICH == 1) ? H_DIM : D_DIM;
    unsigned* Wh = (WHICH == 1) ? g_w1h : g_w2h;
    const long per = (long)KHALF * NDIM;
    const long total = (long)E_NUM * per;
    long w = (long)blockIdx.x * blockDim.x + threadIdx.x;
    if (w < total) {
        int  e  = (int)(w / per);
        long r  = w % per;
        int  kp = (int)(r / NDIM);
        int  n  = (int)(r % NDIM);
        const float* We = W + (size_t)e * 2 * per;
        float v0 = We[(size_t)(2 * kp) * NDIM + n];
        float v1 = We[(size_t)(2 * kp + 1) * NDIM + n];
        Wh[w] = pack2h(v0, v1);
    }
}

// ---------------- GEMM: 64x128 CTA, 8 warps (32x32 tiles), BK=32, 3-stage ----
// Per-stage smem (u32 words): As [64][20] off 0 | Bs [16][136] off 1280
#define OFF_B 1280
#define STAGE_WORDS 3456
#define NSTAGE 3
#define SMEM_BYTES (NSTAGE * STAGE_WORDS * 4)

template <int MODE>   // 1: x @ W1 -> gelu -> hidden(fp16)   2: hidden @ W2 -> out
__global__ void __launch_bounds__(256, 3) moe_gemm(const float* __restrict__ bias_in,
                                                   float* __restrict__ outp) {
    constexpr int KDIM = (MODE == 1) ? D_DIM : H_DIM;
    constexpr int NDIM = (MODE == 1) ? H_DIM : D_DIM;
    constexpr int ASTRIDE = KDIM / 2;
    constexpr int S = KDIM / 32;

    extern __shared__ unsigned smem[];
    const int e  = blockIdx.z;
    const int ne = g_off[e + 1] - g_off[e];
    const int m0 = blockIdx.y * 64;
    if (m0 >= ne) return;
    const int base = g_off[e];
    const int n0 = blockIdx.x * 128;
    const int tid = threadIdx.x;

    const unsigned* Ah = (MODE == 1) ? g_xh : g_hh;
    const unsigned* Bh = ((MODE == 1) ? g_w1h : g_w2h) + (size_t)e * ASTRIDE * NDIM;
    const float* bias = bias_in + (size_t)e * NDIM;

    // ---- per-thread copy mapping ----
    // A: 64 rows x 16 words; one cp16 per thread
    const int rA = tid >> 2, kq = (tid & 3) * 4;
    int ma = m0 + rA; if (ma >= ne) ma = ne - 1;
    size_t arow = (MODE == 1) ? (size_t)g_perm[base + ma] : (size_t)(base + ma);
    const unsigned* aP = Ah + arow * ASTRIDE + kq;
    // B: 16 kp-rows x 128 words; two cp16 per thread
    const int kp0 = tid >> 5, kp1 = kp0 + 8, nq = (tid & 31) * 4;
    const unsigned* bP0 = Bh + (size_t)kp0 * NDIM + n0 + nq;
    const unsigned* bP1 = Bh + (size_t)kp1 * NDIM + n0 + nq;

    const unsigned sbase = (unsigned)__cvta_generic_to_shared(smem);
    const unsigned dA  = (rA * 20 + kq) * 4u;
    const unsigned dB0 = (OFF_B + kp0 * 136 + nq) * 4u;
    const unsigned dB1 = (OFF_B + kp1 * 136 + nq) * 4u;

    auto issue = [&](int buf) {
        unsigned o = sbase + buf * (STAGE_WORDS * 4u);
        cp16(o + dA, aP);
        cp16(o + dB0, bP0);
        cp16(o + dB1, bP1);
        asm volatile("cp.async.commit_group;\n");
        aP += 16;
        bP0 += (size_t)16 * NDIM; bP1 += (size_t)16 * NDIM;
    };

    // ---- warp / fragment mapping: 2x4 warp grid, 32x32 per warp ----
    const int wid = tid >> 5, lane = tid & 31;
    const int grp = lane >> 2, tig = lane & 3;
    const int wm = (wid >> 2) * 32, wn = (wid & 3) * 32;

    float acc[2][4][4];
#pragma unroll
    for (int mi = 0; mi < 2; mi++)
#pragma unroll
        for (int ni = 0; ni < 4; ni++)
#pragma unroll
            for (int j = 0; j < 4; j++) acc[mi][ni][j] = 0.f;

    issue(0);
    issue(1);

    for (int s = 0; s < S; s++) {
        if (s + 1 < S) asm volatile("cp.async.wait_group 1;\n");
        else           asm volatile("cp.async.wait_group 0;\n");
        __syncthreads();
        if (s + 2 < S) issue((s + 2) % NSTAGE);

        const unsigned* As = smem + (s % NSTAGE) * STAGE_WORDS;
        const unsigned* Bs = As + OFF_B;

#pragma unroll
        for (int h = 0; h < 2; h++) {
            const int kb = h * 8;
            unsigned ah[2][4];
#pragma unroll
            for (int mi = 0; mi < 2; mi++) {
                int row = wm + mi * 16 + grp;
                ah[mi][0] = As[row * 20 + kb + tig];
                ah[mi][1] = As[(row + 8) * 20 + kb + tig];
                ah[mi][2] = As[row * 20 + kb + tig + 4];
                ah[mi][3] = As[(row + 8) * 20 + kb + tig + 4];
            }
#pragma unroll
            for (int ni = 0; ni < 4; ni++) {
                int nc = wn + ni * 8 + grp;
                unsigned b0 = Bs[(kb + tig) * 136 + nc];
                unsigned b1 = Bs[(kb + tig + 4) * 136 + nc];
#pragma unroll
                for (int mi = 0; mi < 2; mi++)
                    mma16816h(acc[mi][ni], ah[mi], b0, b1);
            }
        }
    }

    // ---- epilogue ----
#pragma unroll
    for (int mi = 0; mi < 2; mi++) {
#pragma unroll
        for (int ni = 0; ni < 4; ni++) {
            const int mloc = m0 + wm + mi * 16 + grp;
            const int nc = n0 + wn + ni * 8 + tig * 2;
            const float* ac = acc[mi][ni];
            if (MODE == 1) {
                if (mloc < ne) {
                    float v0 = gelu_exact(ac[0] + bias[nc]);
                    float v1 = gelu_exact(ac[1] + bias[nc + 1]);
                    g_hh[(size_t)(base + mloc) * (H_DIM / 2) + (nc >> 1)] = pack2h(v0, v1);
                }
                if (mloc + 8 < ne) {
                    float v0 = gelu_exact(ac[2] + bias[nc]);
                    float v1 = gelu_exact(ac[3] + bias[nc + 1]);
                    g_hh[(size_t)(base + mloc + 8) * (H_DIM / 2) + (nc >> 1)] = pack2h(v0, v1);
                }
            } else {
                if (mloc < ne) {
                    int tok = g_perm[base + mloc]; float ps = g_psel[tok];
                    float2 v = make_float2((ac[0] + bias[nc]) * ps,
                                           (ac[1] + bias[nc + 1]) * ps);
                    *(float2*)&outp[(size_t)tok * D_DIM + nc] = v;
                }
                if (mloc + 8 < ne) {
                    int tok = g_perm[base + mloc + 8]; float ps = g_psel[tok];
                    float2 v = make_float2((ac[2] + bias[nc]) * ps,
                                           (ac[3] + bias[nc + 1]) * ps);
                    *(float2*)&outp[(size_t)tok * D_DIM + nc] = v;
                }
            }
        }
    }
}

// ---------------- launch: gemm1 is our 4th launch (ncu slot) -----------------
extern "C" void kernel_launch(void* const* d_in, const int* in_sizes, int n_in,
                              void* d_out, int out_size) {
    const float* x  = (const float*)d_in[0];
    const float* gw = (const float*)d_in[2];
    const float* W1 = (const float*)d_in[3];
    const float* b1 = (const float*)d_in[4];
    const float* W2 = (const float*)d_in[5];
    const float* b2 = (const float*)d_in[6];
    float* out = (float*)d_out;

    cudaFuncSetAttribute(moe_gemm<1>, cudaFuncAttributeMaxDynamicSharedMemorySize, SMEM_BYTES);
    cudaFuncSetAttribute(moe_gemm<2>, cudaFuncAttributeMaxDynamicSharedMemorySize, SMEM_BYTES);

    routing_kernel<<<T_TOK / 8, 256>>>(x, gw);                          // 1
    finscat_kernel<<<1, 1024>>>(out, out_size);                          // 2
    conv_w_kernel<1><<<(E_NUM * (D_DIM / 2) * H_DIM) / 256, 256>>>(W1);  // 3

    dim3 g1(H_DIM / 128, T_TOK / 64, E_NUM);
    moe_gemm<1><<<g1, 256, SMEM_BYTES>>>(b1, nullptr);                   // 4 <- profile

    conv_w_kernel<2><<<(E_NUM * (H_DIM / 2) * D_DIM) / 256, 256>>>(W2);  // 5

    dim3 g2(D_DIM / 128, T_TOK / 64, E_NUM);
    moe_gemm<2><<<g2, 256, SMEM_BYTES>>>(b2, out);                       // 6
}

// round 15
// speedup vs baseline: 1.0077x; 1.0077x over previous
#include <cuda_runtime.h>
#include <cuda_fp16.h>
#include <math.h>

#define T_TOK 8192
#define D_DIM 768
#define H_DIM 3072
#define E_NUM 8
#define RBLK 1024   // routing grid blocks

// ---------------- device scratch (no allocations allowed) ----------------
__device__ unsigned g_xh[T_TOK * (D_DIM / 2)];          // x fp16 [t][kp]
__device__ unsigned g_w1h[E_NUM * (D_DIM / 2) * H_DIM]; // W1 fp16 [e][kp][n]
__device__ unsigned g_w2h[E_NUM * (H_DIM / 2) * D_DIM]; // W2 fp16 [e][kp][n]
__device__ unsigned g_hh[T_TOK * (H_DIM / 2)];          // hidden fp16 (compact rows)
__device__ int   g_gate[T_TOK];
__device__ float g_psel[T_TOK];
__device__ unsigned long long g_blk_psum[RBLK * E_NUM]; // per-block partials
__device__ int   g_off[E_NUM + 1];
__device__ int   g_perm[T_TOK];

#define PROB_SCALE 4294967296.0

// ---------------- helpers ----------------
__device__ __forceinline__ unsigned pack2h(float v0, float v1) {
    __half2 h = __floats2half2_rn(v0, v1);
    return *(unsigned*)&h;
}
__device__ __forceinline__ float gelu_exact(float v) {
    return 0.5f * v * (1.0f + erff(v * 0.70710678118654752f));
}
__device__ __forceinline__ void mma16816h(float c[4], const unsigned a[4],
                                          unsigned b0, unsigned b1) {
    asm volatile(
        "mma.sync.aligned.m16n8k16.row.col.f32.f16.f16.f32 "
        "{%0,%1,%2,%3}, {%4,%5,%6,%7}, {%8,%9}, {%0,%1,%2,%3};\n"
        : "+f"(c[0]), "+f"(c[1]), "+f"(c[2]), "+f"(c[3])
        : "r"(a[0]), "r"(a[1]), "r"(a[2]), "r"(a[3]), "r"(b0), "r"(b1));
}
__device__ __forceinline__ void cp16(unsigned dst, const void* src) {
    asm volatile("cp.async.cg.shared.global [%0], [%1], 16;\n" :: "r"(dst), "l"(src));
}

// ---------------- K1: routing (1 warp/token) + fused x->fp16 ----------------
__global__ void routing_kernel(const float* __restrict__ x,
                               const float* __restrict__ gw) {
    __shared__ unsigned long long s_probsum[E_NUM];
    int tid = threadIdx.x;
    if (tid < E_NUM) s_probsum[tid] = 0ull;
    __syncthreads();

    int warp = tid >> 5, lane = tid & 31;
    int t = blockIdx.x * 8 + warp;

    float acc[E_NUM];
#pragma unroll
    for (int e = 0; e < E_NUM; e++) acc[e] = 0.f;
    const float* xr = x + (size_t)t * D_DIM;
    for (int kp = lane; kp < D_DIM / 2; kp += 32) {
        float2 v = ((const float2*)xr)[kp];
        g_xh[(size_t)t * (D_DIM / 2) + kp] = pack2h(v.x, v.y);
        const float* g0 = gw + (2 * kp) * E_NUM;
#pragma unroll
        for (int e = 0; e < E_NUM; e++)
            acc[e] += v.x * g0[e] + v.y * g0[e + E_NUM];
    }
#pragma unroll
    for (int off = 16; off > 0; off >>= 1) {
#pragma unroll
        for (int e = 0; e < E_NUM; e++)
            acc[e] += __shfl_xor_sync(0xffffffffu, acc[e], off);
    }

    if (lane == 0) {
        float mx = acc[0]; int am = 0;
#pragma unroll
        for (int e = 1; e < E_NUM; e++) if (acc[e] > mx) { mx = acc[e]; am = e; }
        float p[E_NUM]; float s = 0.f;
#pragma unroll
        for (int e = 0; e < E_NUM; e++) { p[e] = expf(acc[e] - mx); s += p[e]; }
        float inv = 1.f / s;
#pragma unroll
        for (int e = 0; e < E_NUM; e++) {
            double pq = (double)(p[e] * inv) * PROB_SCALE;
            atomicAdd(&s_probsum[e], (unsigned long long)(pq + 0.5));
        }
        g_gate[t] = am;
        g_psel[t] = p[am] * inv;
    }
    __syncthreads();
    if (tid < E_NUM)
        g_blk_psum[blockIdx.x * E_NUM + tid] = s_probsum[tid];
}

// ---------------- K2: deterministic scan -> sorted perm + loss + tail --------
__global__ void __launch_bounds__(1024) finscat_kernel(float* __restrict__ out,
                                                       int out_size) {
    __shared__ unsigned long long s0[1024], s1[1024];
    const int tid = threadIdx.x;
    const int t0 = tid * 8;

    // per-thread counts over 8 contiguous tokens
    int ge[8];
    int c[E_NUM];
#pragma unroll
    for (int e = 0; e < E_NUM; e++) c[e] = 0;
#pragma unroll
    for (int i = 0; i < 8; i++) { ge[i] = g_gate[t0 + i]; c[ge[i]]++; }

    unsigned long long p0 = 0, p1 = 0;
#pragma unroll
    for (int e = 0; e < 4; e++) {
        p0 |= (unsigned long long)c[e]     << (16 * e);
        p1 |= (unsigned long long)c[e + 4] << (16 * e);
    }
    s0[tid] = p0; s1[tid] = p1;
    __syncthreads();

    // Hillis-Steele inclusive scan (packed 8x16-bit, max 8192 < 65536)
    for (int off = 1; off < 1024; off <<= 1) {
        unsigned long long a0 = 0, a1 = 0;
        if (tid >= off) { a0 = s0[tid - off]; a1 = s1[tid - off]; }
        __syncthreads();
        s0[tid] += a0; s1[tid] += a1;
        __syncthreads();
    }
    const unsigned long long tot0 = s0[1023], tot1 = s1[1023];
    const unsigned long long inc0 = s0[tid],  inc1 = s1[tid];

    int cnt[E_NUM], excl[E_NUM];
#pragma unroll
    for (int e = 0; e < 4; e++) {
        cnt[e]      = (int)((tot0 >> (16 * e)) & 0xFFFF);
        cnt[e + 4]  = (int)((tot1 >> (16 * e)) & 0xFFFF);
        excl[e]     = (int)((inc0 >> (16 * e)) & 0xFFFF) - c[e];
        excl[e + 4] = (int)((inc1 >> (16 * e)) & 0xFFFF) - c[e + 4];
    }
    int offp[E_NUM]; int run = 0;
#pragma unroll
    for (int e = 0; e < E_NUM; e++) { offp[e] = run; run += cnt[e]; }

    // psum reduce (deterministic tree): expert = tid>>7, 128 threads each
    __syncthreads();
    {
        unsigned long long ps = 0;
        const int e = tid >> 7, j = tid & 127;
        for (int i = j; i < RBLK; i += 128) ps += g_blk_psum[i * E_NUM + e];
        s0[tid] = ps;
        __syncthreads();
        for (int st = 64; st > 0; st >>= 1) {
            if (j < st) s0[tid] += s0[tid + st];
            __syncthreads();
        }
    }

    if (tid == 0) {
#pragma unroll
        for (int e = 0; e < E_NUM; e++) g_off[e] = offp[e];
        g_off[E_NUM] = T_TOK;

        float loss = 0.f;
        const float invT = 1.0f / (float)T_TOK;
#pragma unroll
        for (int e = 0; e < E_NUM; e++) {
            float ps = (float)((double)s0[e << 7] / PROB_SCALE);
            loss += (ps * invT) * ((float)cnt[e] * invT);
        }
        loss *= (float)E_NUM;

        int base = T_TOK * D_DIM;
        if (out_size > base) out[base] = loss;
#pragma unroll
        for (int e = 0; e < E_NUM; e++)
            if (out_size > base + 1 + e) out[base + 1 + e] = (float)cnt[e];
    }

    // write sorted-by-token permutation
    int cur[E_NUM];
#pragma unroll
    for (int e = 0; e < E_NUM; e++) cur[e] = offp[e] + excl[e];
#pragma unroll
    for (int i = 0; i < 8; i++) {
        int e = ge[i];
        g_perm[cur[e]++] = t0 + i;
    }
}

// ---------------- K5: weights -> fp16 k-pair packed [e][kp][n] ----------------
template <int WHICH>
__global__ void conv_w_kernel(const float* __restrict__ W) {
    constexpr int KHALF = (WHICH == 1) ? D_DIM / 2 : H_DIM / 2;
    constexpr int NDIM  = (WHICH == 1) ? H_DIM : D_DIM;
    unsigned* Wh = (WHICH == 1) ? g_w1h : g_w2h;
    const long per = (long)KHALF * NDIM;
    const long total = (long)E_NUM * per;
    long w = (long)blockIdx.x * blockDim.x + threadIdx.x;
    if (w < total) {
        int  e  = (int)(w / per);
        long r  = w % per;
        int  kp = (int)(r / NDIM);
        int  n  = (int)(r % NDIM);
        const float* We = W + (size_t)e * 2 * per;
        float v0 = We[(size_t)(2 * kp) * NDIM + n];
        float v1 = We[(size_t)(2 * kp + 1) * NDIM + n];
        Wh[w] = pack2h(v0, v1);
    }
}

// ---------------- GEMM: 64x128 CTA, 8 warps (32x32 tiles), BK=32, 3-stage ----
// Per-stage smem (u32 words): As [64][20] off 0 | Bs [16][136] off 1280
#define OFF_B 1280
#define STAGE_WORDS 3456
#define NSTAGE 3
#define SMEM_BYTES (NSTAGE * STAGE_WORDS * 4)

template <int MODE>   // 1: x @ W1 -> gelu -> hidden(fp16)   2: hidden @ W2 -> out
__global__ void __launch_bounds__(256, 3) moe_gemm(const float* __restrict__ bias_in,
                                                   float* __restrict__ outp) {
    constexpr int KDIM = (MODE == 1) ? D_DIM : H_DIM;
    constexpr int NDIM = (MODE == 1) ? H_DIM : D_DIM;
    constexpr int ASTRIDE = KDIM / 2;
    constexpr int S = KDIM / 32;

    extern __shared__ unsigned smem[];
    const int e  = blockIdx.z;
    const int ne = g_off[e + 1] - g_off[e];
    const int m0 = blockIdx.y * 64;
    if (m0 >= ne) return;
    const int base = g_off[e];
    const int n0 = blockIdx.x * 128;
    const int tid = threadIdx.x;

    const unsigned* Ah = (MODE == 1) ? g_xh : g_hh;
    const unsigned* Bh = ((MODE == 1) ? g_w1h : g_w2h) + (size_t)e * ASTRIDE * NDIM;
    const float* bias = bias_in + (size_t)e * NDIM;

    // ---- per-thread copy mapping ----
    // A: 64 rows x 16 words; one cp16 per thread
    const int rA = tid >> 2, kq = (tid & 3) * 4;
    int ma = m0 + rA; if (ma >= ne) ma = ne - 1;
    size_t arow = (MODE == 1) ? (size_t)g_perm[base + ma] : (size_t)(base + ma);
    const unsigned* aP = Ah + arow * ASTRIDE + kq;
    // B: 16 kp-rows x 128 words; two cp16 per thread
    const int kp0 = tid >> 5, kp1 = kp0 + 8, nq = (tid & 31) * 4;
    const unsigned* bP0 = Bh + (size_t)kp0 * NDIM + n0 + nq;
    const unsigned* bP1 = Bh + (size_t)kp1 * NDIM + n0 + nq;

    const unsigned sbase = (unsigned)__cvta_generic_to_shared(smem);
    const unsigned dA  = (rA * 20 + kq) * 4u;
    const unsigned dB0 = (OFF_B + kp0 * 136 + nq) * 4u;
    const unsigned dB1 = (OFF_B + kp1 * 136 + nq) * 4u;

    auto issue = [&](int buf) {
        unsigned o = sbase + buf * (STAGE_WORDS * 4u);
        cp16(o + dA, aP);
        cp16(o + dB0, bP0);
        cp16(o + dB1, bP1);
        asm volatile("cp.async.commit_group;\n");
        aP += 16;
        bP0 += (size_t)16 * NDIM; bP1 += (size_t)16 * NDIM;
    };

    // ---- warp / fragment mapping: 2x4 warp grid, 32x32 per warp ----
    const int wid = tid >> 5, lane = tid & 31;
    const int grp = lane >> 2, tig = lane & 3;
    const int wm = (wid >> 2) * 32, wn = (wid & 3) * 32;

    float acc[2][4][4];
#pragma unroll
    for (int mi = 0; mi < 2; mi++)
#pragma unroll
        for (int ni = 0; ni < 4; ni++)
#pragma unroll
            for (int j = 0; j < 4; j++) acc[mi][ni][j] = 0.f;

    issue(0);
    issue(1);

    for (int s = 0; s < S; s++) {
        if (s + 1 < S) asm volatile("cp.async.wait_group 1;\n");
        else           asm volatile("cp.async.wait_group 0;\n");
        __syncthreads();
        if (s + 2 < S) issue((s + 2) % NSTAGE);

        const unsigned* As = smem + (s % NSTAGE) * STAGE_WORDS;
        const unsigned* Bs = As + OFF_B;

#pragma unroll
        for (int h = 0; h < 2; h++) {
            const int kb = h * 8;
            unsigned ah[2][4];
#pragma unroll
            for (int mi = 0; mi < 2; mi++) {
                int row = wm + mi * 16 + grp;
                ah[mi][0] = As[row * 20 + kb + tig];
                ah[mi][1] = As[(row + 8) * 20 + kb + tig];
                ah[mi][2] = As[row * 20 + kb + tig + 4];
                ah[mi][3] = As[(row + 8) * 20 + kb + tig + 4];
            }
#pragma unroll
            for (int ni = 0; ni < 4; ni++) {
                int nc = wn + ni * 8 + grp;
                unsigned b0 = Bs[(kb + tig) * 136 + nc];
                unsigned b1 = Bs[(kb + tig + 4) * 136 + nc];
#pragma unroll
                for (int mi = 0; mi < 2; mi++)
                    mma16816h(acc[mi][ni], ah[mi], b0, b1);
            }
        }
    }

    // ---- epilogue ----
#pragma unroll
    for (int mi = 0; mi < 2; mi++) {
#pragma unroll
        for (int ni = 0; ni < 4; ni++) {
            const int mloc = m0 + wm + mi * 16 + grp;
            const int nc = n0 + wn + ni * 8 + tig * 2;
            const float* ac = acc[mi][ni];
            if (MODE == 1) {
                if (mloc < ne) {
                    float v0 = gelu_exact(ac[0] + bias[nc]);
                    float v1 = gelu_exact(ac[1] + bias[nc + 1]);
                    g_hh[(size_t)(base + mloc) * (H_DIM / 2) + (nc >> 1)] = pack2h(v0, v1);
                }
                if (mloc + 8 < ne) {
                    float v0 = gelu_exact(ac[2] + bias[nc]);
                    float v1 = gelu_exact(ac[3] + bias[nc + 1]);
                    g_hh[(size_t)(base + mloc + 8) * (H_DIM / 2) + (nc >> 1)] = pack2h(v0, v1);
                }
            } else {
                if (mloc < ne) {
                    int tok = g_perm[base + mloc]; float ps = g_psel[tok];
                    float2 v = make_float2((ac[0] + bias[nc]) * ps,
                                           (ac[1] + bias[nc + 1]) * ps);
                    *(float2*)&outp[(size_t)tok * D_DIM + nc] = v;
                }
                if (mloc + 8 < ne) {
                    int tok = g_perm[base + mloc + 8]; float ps = g_psel[tok];
                    float2 v = make_float2((ac[2] + bias[nc]) * ps,
                                           (ac[3] + bias[nc + 1]) * ps);
                    *(float2*)&outp[(size_t)tok * D_DIM + nc] = v;
                }
            }
        }
    }
}

// ---------------- launch: gemm1 is our 4th launch (ncu slot) -----------------
extern "C" void kernel_launch(void* const* d_in, const int* in_sizes, int n_in,
                              void* d_out, int out_size) {
    const float* x  = (const float*)d_in[0];
    const float* gw = (const float*)d_in[2];
    const float* W1 = (const float*)d_in[3];
    const float* b1 = (const float*)d_in[4];
    const float* W2 = (const float*)d_in[5];
    const float* b2 = (const float*)d_in[6];
    float* out = (float*)d_out;

    cudaFuncSetAttribute(moe_gemm<1>, cudaFuncAttributeMaxDynamicSharedMemorySize, SMEM_BYTES);
    cudaFuncSetAttribute(moe_gemm<2>, cudaFuncAttributeMaxDynamicSharedMemorySize, SMEM_BYTES);

    routing_kernel<<<T_TOK / 8, 256>>>(x, gw);                          // 1
    finscat_kernel<<<1, 1024>>>(out, out_size);                          // 2
    conv_w_kernel<1><<<(E_NUM * (D_DIM / 2) * H_DIM) / 256, 256>>>(W1);  // 3

    dim3 g1(H_DIM / 128, T_TOK / 64, E_NUM);
    moe_gemm<1><<<g1, 256, SMEM_BYTES>>>(b1, nullptr);                   // 4 <- profile

    conv_w_kernel<2><<<(E_NUM * (H_DIM / 2) * D_DIM) / 256, 256>>>(W2);  // 5

    dim3 g2(D_DIM / 128, T_TOK / 64, E_NUM);
    moe_gemm<2><<<g2, 256, SMEM_BYTES>>>(b2, out);                       // 6
}

// round 16
// speedup vs baseline: 1.0996x; 1.0912x over previous
#include <cuda_runtime.h>
#include <cuda_fp16.h>
#include <math.h>

#define T_TOK 8192
#define D_DIM 768
#define H_DIM 3072
#define E_NUM 8
#define RBLK 1024          // routing blocks inside prep_kernel
#define CONV_BLKS 9216     // E*(D/2)*H / (256*4) = per conv
#define PREP_BLKS (RBLK + 2 * CONV_BLKS)

// ---------------- device scratch (no allocations allowed) ----------------
__device__ __align__(16) unsigned g_xh[T_TOK * (D_DIM / 2)];          // x fp16 [t][kp]
__device__ __align__(16) unsigned g_w1h[E_NUM * (D_DIM / 2) * H_DIM]; // W1 fp16 [e][kp][n]
__device__ __align__(16) unsigned g_w2h[E_NUM * (H_DIM / 2) * D_DIM]; // W2 fp16 [e][kp][n]
__device__ __align__(16) unsigned g_hh[T_TOK * (H_DIM / 2)];          // hidden fp16
__device__ int   g_gate[T_TOK];
__device__ float g_psel[T_TOK];
__device__ int   g_blk_cnt[RBLK * E_NUM];               // per-block partials (overwritten)
__device__ unsigned long long g_blk_psum[RBLK * E_NUM];
__device__ int   g_off[E_NUM + 1];
__device__ int   g_cursor[E_NUM];
__device__ int   g_perm[T_TOK];

#define PROB_SCALE 4294967296.0

// ---------------- helpers ----------------
__device__ __forceinline__ unsigned pack2h(float v0, float v1) {
    __half2 h = __floats2half2_rn(v0, v1);
    return *(unsigned*)&h;
}
__device__ __forceinline__ float gelu_exact(float v) {
    return 0.5f * v * (1.0f + erff(v * 0.70710678118654752f));
}
__device__ __forceinline__ void mma16816h(float c[4], const unsigned a[4],
                                          unsigned b0, unsigned b1) {
    asm volatile(
        "mma.sync.aligned.m16n8k16.row.col.f32.f16.f16.f32 "
        "{%0,%1,%2,%3}, {%4,%5,%6,%7}, {%8,%9}, {%0,%1,%2,%3};\n"
        : "+f"(c[0]), "+f"(c[1]), "+f"(c[2]), "+f"(c[3])
        : "r"(a[0]), "r"(a[1]), "r"(a[2]), "r"(a[3]), "r"(b0), "r"(b1));
}
__device__ __forceinline__ void cp16(unsigned dst, const void* src) {
    asm volatile("cp.async.cg.shared.global [%0], [%1], 16;\n" :: "r"(dst), "l"(src));
}

// ---------------- conv helper: 4 consecutive words of [e][kp][n] -------------
__device__ __forceinline__ void conv_w4(const float* __restrict__ W, unsigned* Wh,
                                        long w, int KHALF, int NDIM) {
    const long per = (long)KHALF * NDIM;
    int  e  = (int)(w / per);
    long r  = w % per;
    int  kp = (int)(r / NDIM);
    int  n  = (int)(r % NDIM);
    const float* We = W + (size_t)e * 2 * per;
    float4 a = *(const float4*)(We + (size_t)(2 * kp) * NDIM + n);
    float4 b = *(const float4*)(We + (size_t)(2 * kp + 1) * NDIM + n);
    uint4 o;
    o.x = pack2h(a.x, b.x);
    o.y = pack2h(a.y, b.y);
    o.z = pack2h(a.z, b.z);
    o.w = pack2h(a.w, b.w);
    *(uint4*)(Wh + w) = o;
}

// ---------------- K1: fused routing + conv_x + conv_w1 + conv_w2 -------------
__global__ void __launch_bounds__(256) prep_kernel(const float* __restrict__ x,
                                                   const float* __restrict__ gw,
                                                   const float* __restrict__ W1,
                                                   const float* __restrict__ W2) {
    const int bx = blockIdx.x;
    const int tid = threadIdx.x;

    if (bx >= RBLK) {
        // ---- weight conversion blocks ----
        if (bx < RBLK + CONV_BLKS) {
            long w = ((long)(bx - RBLK) * 256 + tid) * 4;
            conv_w4(W1, g_w1h, w, D_DIM / 2, H_DIM);
        } else {
            long w = ((long)(bx - RBLK - CONV_BLKS) * 256 + tid) * 4;
            conv_w4(W2, g_w2h, w, H_DIM / 2, D_DIM);
        }
        return;
    }

    // ---- routing block (8 warps, 1 token each) ----
    __shared__ unsigned long long s_probsum[E_NUM];
    __shared__ int                s_counts[E_NUM];
    if (tid < E_NUM) { s_probsum[tid] = 0ull; s_counts[tid] = 0; }
    __syncthreads();

    int warp = tid >> 5, lane = tid & 31;
    int t = bx * 8 + warp;

    float acc[E_NUM];
#pragma unroll
    for (int e = 0; e < E_NUM; e++) acc[e] = 0.f;
    const float* xr = x + (size_t)t * D_DIM;
    for (int kp = lane; kp < D_DIM / 2; kp += 32) {
        float2 v = ((const float2*)xr)[kp];
        g_xh[(size_t)t * (D_DIM / 2) + kp] = pack2h(v.x, v.y);
        const float* g0 = gw + (2 * kp) * E_NUM;
#pragma unroll
        for (int e = 0; e < E_NUM; e++)
            acc[e] += v.x * g0[e] + v.y * g0[e + E_NUM];
    }
#pragma unroll
    for (int off = 16; off > 0; off >>= 1) {
#pragma unroll
        for (int e = 0; e < E_NUM; e++)
            acc[e] += __shfl_xor_sync(0xffffffffu, acc[e], off);
    }

    if (lane == 0) {
        float mx = acc[0]; int am = 0;
#pragma unroll
        for (int e = 1; e < E_NUM; e++) if (acc[e] > mx) { mx = acc[e]; am = e; }
        float p[E_NUM]; float s = 0.f;
#pragma unroll
        for (int e = 0; e < E_NUM; e++) { p[e] = expf(acc[e] - mx); s += p[e]; }
        float inv = 1.f / s;
#pragma unroll
        for (int e = 0; e < E_NUM; e++) {
            double pq = (double)(p[e] * inv) * PROB_SCALE;
            atomicAdd(&s_probsum[e], (unsigned long long)(pq + 0.5));
        }
        atomicAdd(&s_counts[am], 1);
        g_gate[t] = am;
        g_psel[t] = p[am] * inv;
    }
    __syncthreads();
    if (tid < E_NUM) {
        g_blk_psum[bx * E_NUM + tid] = s_probsum[tid];
        g_blk_cnt[bx * E_NUM + tid]  = s_counts[tid];
    }
}

// ---------------- K2: deterministic reduce -> offsets + loss + tail ----------
__global__ void __launch_bounds__(1024) finalize_kernel(float* __restrict__ out,
                                                        int out_size) {
    __shared__ unsigned long long sp[1024];
    __shared__ int sc[1024];
    __shared__ unsigned long long t_ps[E_NUM];
    __shared__ int t_cnt[E_NUM];
    const int tid = threadIdx.x;

#pragma unroll
    for (int e = 0; e < E_NUM; e++) {
        sp[tid] = g_blk_psum[tid * E_NUM + e];
        sc[tid] = g_blk_cnt[tid * E_NUM + e];
        __syncthreads();
        for (int s = 512; s > 0; s >>= 1) {
            if (tid < s) { sp[tid] += sp[tid + s]; sc[tid] += sc[tid + s]; }
            __syncthreads();
        }
        if (tid == 0) { t_ps[e] = sp[0]; t_cnt[e] = sc[0]; }
        __syncthreads();
    }

    if (tid == 0) {
        int off = 0;
#pragma unroll
        for (int e = 0; e < E_NUM; e++) {
            g_off[e] = off; g_cursor[e] = off; off += t_cnt[e];
        }
        g_off[E_NUM] = off;

        float loss = 0.f;
        const float invT = 1.0f / (float)T_TOK;
#pragma unroll
        for (int e = 0; e < E_NUM; e++) {
            float ps = (float)((double)t_ps[e] / PROB_SCALE);
            loss += (ps * invT) * ((float)t_cnt[e] * invT);
        }
        loss *= (float)E_NUM;

        int base = T_TOK * D_DIM;
        if (out_size > base) out[base] = loss;
#pragma unroll
        for (int e = 0; e < E_NUM; e++)
            if (out_size > base + 1 + e) out[base + 1 + e] = (float)t_cnt[e];
    }
}

// ---------------- K3: per-expert compact permutation (parallel) --------------
__global__ void scatter_kernel() {
    int t = blockIdx.x * blockDim.x + threadIdx.x;
    if (t < T_TOK) {
        int e = g_gate[t];
        int pos = atomicAdd(&g_cursor[e], 1);
        g_perm[pos] = t;
    }
}

// ---------------- GEMM: 128x128 CTA, 8 warps (32x64 tiles), BK=32, 3-stage ---
// (byte-identical mainloop to the 483us R8 champion)
#define OFF_B 2560
#define STAGE_WORDS 4736
#define NSTAGE 3
#define SMEM_BYTES (NSTAGE * STAGE_WORDS * 4)

template <int MODE>   // 1: x @ W1 -> gelu -> hidden(fp16)   2: hidden @ W2 -> out
__global__ void __launch_bounds__(256, 2) moe_gemm(const float* __restrict__ bias_in,
                                                   float* __restrict__ outp) {
    constexpr int KDIM = (MODE == 1) ? D_DIM : H_DIM;
    constexpr int NDIM = (MODE == 1) ? H_DIM : D_DIM;
    constexpr int ASTRIDE = KDIM / 2;
    constexpr int S = KDIM / 32;

    extern __shared__ unsigned smem[];
    const int e  = blockIdx.z;
    const int ne = g_off[e + 1] - g_off[e];
    const int m0 = blockIdx.y * 128;
    if (m0 >= ne) return;
    const int base = g_off[e];
    const int n0 = blockIdx.x * 128;
    const int tid = threadIdx.x;

    const unsigned* Ah = (MODE == 1) ? g_xh : g_hh;
    const unsigned* Bh = ((MODE == 1) ? g_w1h : g_w2h) + (size_t)e * ASTRIDE * NDIM;
    const float* bias = bias_in + (size_t)e * NDIM;

    const int r0 = tid >> 2, kq = (tid & 3) * 4;
    const int r1 = r0 + 64;
    int ma0 = m0 + r0; if (ma0 >= ne) ma0 = ne - 1;
    int ma1 = m0 + r1; if (ma1 >= ne) ma1 = ne - 1;
    size_t arow0, arow1;
    if (MODE == 1) { arow0 = (size_t)g_perm[base + ma0]; arow1 = (size_t)g_perm[base + ma1]; }
    else           { arow0 = (size_t)(base + ma0);       arow1 = (size_t)(base + ma1); }
    const unsigned* aH0 = Ah + arow0 * ASTRIDE + kq;
    const unsigned* aH1 = Ah + arow1 * ASTRIDE + kq;

    const int kpA = tid >> 5, kpB2 = kpA + 8, nq = (tid & 31) * 4;
    const unsigned* bH0 = Bh + (size_t)kpA * NDIM + n0 + nq;
    const unsigned* bH1 = Bh + (size_t)kpB2 * NDIM + n0 + nq;

    const unsigned sbase = (unsigned)__cvta_generic_to_shared(smem);
    const unsigned dA0 = (r0 * 20 + kq) * 4u, dA1 = (r1 * 20 + kq) * 4u;
    const unsigned dB0 = (OFF_B + kpA * 136 + nq) * 4u, dB1 = (OFF_B + kpB2 * 136 + nq) * 4u;

    auto issue = [&](int buf) {
        unsigned o = sbase + buf * (STAGE_WORDS * 4u);
        cp16(o + dA0, aH0);
        cp16(o + dA1, aH1);
        cp16(o + dB0, bH0);
        cp16(o + dB1, bH1);
        asm volatile("cp.async.commit_group;\n");
        aH0 += 16; aH1 += 16;
        bH0 += (size_t)16 * NDIM; bH1 += (size_t)16 * NDIM;
    };

    const int wid = tid >> 5, lane = tid & 31;
    const int grp = lane >> 2, tig = lane & 3;
    const int wm = (wid >> 1) * 32, wn = (wid & 1) * 64;

    float acc[2][8][4];
#pragma unroll
    for (int mi = 0; mi < 2; mi++)
#pragma unroll
        for (int ni = 0; ni < 8; ni++)
#pragma unroll
            for (int j = 0; j < 4; j++) acc[mi][ni][j] = 0.f;

    issue(0);
    issue(1);

    for (int s = 0; s < S; s++) {
        if (s + 1 < S) asm volatile("cp.async.wait_group 1;\n");
        else           asm volatile("cp.async.wait_group 0;\n");
        __syncthreads();
        if (s + 2 < S) issue((s + 2) % NSTAGE);

        const unsigned* As = smem + (s % NSTAGE) * STAGE_WORDS;
        const unsigned* Bs = As + OFF_B;

#pragma unroll
        for (int h = 0; h < 2; h++) {
            const int kb = h * 8;
            unsigned ah[2][4];
#pragma unroll
            for (int mi = 0; mi < 2; mi++) {
                int row = wm + mi * 16 + grp;
                ah[mi][0] = As[row * 20 + kb + tig];
                ah[mi][1] = As[(row + 8) * 20 + kb + tig];
                ah[mi][2] = As[row * 20 + kb + tig + 4];
                ah[mi][3] = As[(row + 8) * 20 + kb + tig + 4];
            }
#pragma unroll
            for (int ni = 0; ni < 8; ni++) {
                int nc = wn + ni * 8 + grp;
                unsigned b0 = Bs[(kb + tig) * 136 + nc];
                unsigned b1 = Bs[(kb + tig + 4) * 136 + nc];
#pragma unroll
                for (int mi = 0; mi < 2; mi++)
                    mma16816h(acc[mi][ni], ah[mi], b0, b1);
            }
        }
    }

    // ---- epilogue ----
#pragma unroll
    for (int mi = 0; mi < 2; mi++) {
#pragma unroll
        for (int ni = 0; ni < 8; ni++) {
            const int mloc = m0 + wm + mi * 16 + grp;
            const int nc = n0 + wn + ni * 8 + tig * 2;
            const float* ac = acc[mi][ni];
            if (MODE == 1) {
                if (mloc < ne) {
                    float v0 = gelu_exact(ac[0] + bias[nc]);
                    float v1 = gelu_exact(ac[1] + bias[nc + 1]);
                    g_hh[(size_t)(base + mloc) * (H_DIM / 2) + (nc >> 1)] = pack2h(v0, v1);
                }
                if (mloc + 8 < ne) {
                    float v0 = gelu_exact(ac[2] + bias[nc]);
                    float v1 = gelu_exact(ac[3] + bias[nc + 1]);
                    g_hh[(size_t)(base + mloc + 8) * (H_DIM / 2) + (nc >> 1)] = pack2h(v0, v1);
                }
            } else {
                if (mloc < ne) {
                    int tok = g_perm[base + mloc]; float ps = g_psel[tok];
                    float2 v = make_float2((ac[0] + bias[nc]) * ps,
                                           (ac[1] + bias[nc + 1]) * ps);
                    *(float2*)&outp[(size_t)tok * D_DIM + nc] = v;
                }
                if (mloc + 8 < ne) {
                    int tok = g_perm[base + mloc + 8]; float ps = g_psel[tok];
                    float2 v = make_float2((ac[2] + bias[nc]) * ps,
                                           (ac[3] + bias[nc + 1]) * ps);
                    *(float2*)&outp[(size_t)tok * D_DIM + nc] = v;
                }
            }
        }
    }
}

// ---------------- launch: gemm1 is our 4th launch (ncu slot) -----------------
extern "C" void kernel_launch(void* const* d_in, const int* in_sizes, int n_in,
                              void* d_out, int out_size) {
    const float* x  = (const float*)d_in[0];
    const float* gw = (const float*)d_in[2];
    const float* W1 = (const float*)d_in[3];
    const float* b1 = (const float*)d_in[4];
    const float* W2 = (const float*)d_in[5];
    const float* b2 = (const float*)d_in[6];
    float* out = (float*)d_out;

    cudaFuncSetAttribute(moe_gemm<1>, cudaFuncAttributeMaxDynamicSharedMemorySize, SMEM_BYTES);
    cudaFuncSetAttribute(moe_gemm<2>, cudaFuncAttributeMaxDynamicSharedMemorySize, SMEM_BYTES);

    prep_kernel<<<PREP_BLKS, 256>>>(x, gw, W1, W2);          // 1: routing + all conversions
    finalize_kernel<<<1, 1024>>>(out, out_size);             // 2
    scatter_kernel<<<T_TOK / 256, 256>>>();                  // 3

    dim3 g1(H_DIM / 128, T_TOK / 128, E_NUM);
    moe_gemm<1><<<g1, 256, SMEM_BYTES>>>(b1, nullptr);       // 4 <- profile

    dim3 g2(D_DIM / 128, T_TOK / 128, E_NUM);
    moe_gemm<2><<<g2, 256, SMEM_BYTES>>>(b2, out);           // 5
}